// round 17
// baseline (speedup 1.0000x reference)
#include <cuda_runtime.h>
#include <cuda_fp16.h>
#include <math.h>
#include <stdint.h>

// ---------------- problem constants ----------------
namespace {
constexpr int B = 4, H = 64, W = 64, C = 768;
constexpr int HEADS = 12, HD = 64, WS = 14, HID = 3072;
constexpr int NWIN = 5;               // 70/14
constexpr int NWB  = NWIN * NWIN;     // 25 windows per batch
constexpr int NW   = B * NWB;         // 100 windows
constexpr int L    = WS * WS;         // 196 tokens per window
constexpr int NT   = NW * L;          // 19600 window tokens
constexpr int NP   = B * H * W;       // 16384 real pixels
constexpr int C3   = 3 * C;           // 2304
constexpr int RELN = 2 * WS - 1;      // 27
constexpr float EPS   = 1e-6f;
constexpr float SCALE = 0.125f;       // HD^-0.5
}

// ---------------- scratch (device globals; no allocation allowed) --------
__device__ __half g_ywin_h[(size_t)NT * C];    // LN1 out (window layout, fp16)
__device__ __half g_qkv_h[(size_t)NT * C3];    // qkv (fp16)
__device__ __half g_owin_h[(size_t)NT * C];    // attention out (fp16)
__device__ float  g_x1   [(size_t)NP * C];     // shortcut + proj(o)
__device__ __half g_h2_h [(size_t)NP * C];     // LN2 out (fp16)
__device__ __half g_m1_h [(size_t)NP * HID];   // gelu(fc1) (fp16)
// fp16 TRANSPOSED weights [N, K]
__device__ __half g_qkvw_t[(size_t)C3 * C];
__device__ __half g_projw_t[(size_t)C * C];
__device__ __half g_fc1w_t[(size_t)HID * C];
__device__ __half g_fc2w_t[(size_t)C * HID];

// window-row -> pixel-row index (-1 if padded)
__device__ __forceinline__ int winrow_to_pixel(int t) {
    int nw = t / L, l = t - nw * L;
    int b  = nw / NWB, r = nw - b * NWB;
    int wi = r / NWIN, wj = r - wi * NWIN;
    int i  = l / WS,   j  = l - i * WS;
    int hh = wi * WS + i, ww = wj * WS + j;
    if (hh >= H || ww >= W) return -1;
    return (b * H + hh) * W + ww;
}

__device__ __forceinline__ void mma_f16(float c[4], const uint32_t a[4],
                                        const uint32_t b0, const uint32_t b1) {
    asm volatile(
        "mma.sync.aligned.m16n8k16.row.col.f32.f16.f16.f32 "
        "{%0,%1,%2,%3}, {%4,%5,%6,%7}, {%8,%9}, {%0,%1,%2,%3};"
        : "+f"(c[0]), "+f"(c[1]), "+f"(c[2]), "+f"(c[3])
        : "r"(a[0]), "r"(a[1]), "r"(a[2]), "r"(a[3]), "r"(b0), "r"(b1));
}

__device__ __forceinline__ void ldsm_x4(uint32_t (&r)[4], uint32_t addr) {
    asm volatile(
        "ldmatrix.sync.aligned.m8n8.x4.shared.b16 {%0,%1,%2,%3}, [%4];"
        : "=r"(r[0]), "=r"(r[1]), "=r"(r[2]), "=r"(r[3]) : "r"(addr));
}

__device__ __forceinline__ uint32_t smem_u32(const void* p) {
    uint32_t a;
    asm("{ .reg .u64 t; cvta.to.shared.u64 t, %1; cvt.u32.u64 %0, t; }"
        : "=r"(a) : "l"(p));
    return a;
}

// fast exact-enough gelu: tanh form with HW tanh.approx (MUFU)
__device__ __forceinline__ float fast_gelu(float v) {
    float u = 0.7978845608028654f * (v + 0.044715f * v * v * v);
    float t;
    asm("tanh.approx.f32 %0, %1;" : "=f"(t) : "f"(u));
    return 0.5f * v * (1.f + t);
}

// ---------------- batched weight transpose (all 4 weights, 1 launch) -------
__device__ __forceinline__ void wt_body(const float* __restrict__ w,
                                        __half* __restrict__ wt,
                                        int K, int N, int b) {
    __shared__ float s[32][33];
    int nx = N / 32;
    int n0 = (b % nx) * 32, k0 = (b / nx) * 32;
    int tx = threadIdx.x, ty = threadIdx.y;   // 32 x 8
#pragma unroll
    for (int i = 0; i < 32; i += 8)
        s[ty + i][tx] = w[(size_t)(k0 + ty + i) * N + n0 + tx];
    __syncthreads();
#pragma unroll
    for (int i = 0; i < 32; i += 8)
        wt[(size_t)(n0 + ty + i) * K + k0 + tx] = __float2half(s[tx][ty + i]);
}

__global__ void wt_all_kernel(const float* w0, __half* t0,
                              const float* w1, __half* t1,
                              const float* w2, __half* t2,
                              const float* w3, __half* t3) {
    constexpr int B0 = (C3 / 32) * (C / 32);    // qkv  1728
    constexpr int B1 = (C / 32) * (C / 32);     // proj 576
    constexpr int B2 = (HID / 32) * (C / 32);   // fc1  2304
    int b = blockIdx.x;
    if (b < B0)                { wt_body(w0, t0, C,   C3,  b); return; }
    b -= B0;
    if (b < B1)                { wt_body(w1, t1, C,   C,   b); return; }
    b -= B1;
    if (b < B2)                { wt_body(w2, t2, C,   HID, b); return; }
    b -= B2;
    wt_body(w3, t3, HID, C, b);
}
constexpr int WT_BLOCKS = (C3 / 32) * (C / 32) + (C / 32) * (C / 32) +
                          (HID / 32) * (C / 32) + (C / 32) * (HID / 32);

// ---------------- LN1 + window gather (fp16 out, zero-fill padding) -------
__global__ void ln1_gather_kernel(const float* __restrict__ x,
                                  const float* __restrict__ sc,
                                  const float* __restrict__ bi) {
    int t = blockIdx.x;
    int tid = threadIdx.x;
    __half* y = g_ywin_h + (size_t)t * C;
    int pix = winrow_to_pixel(t);
    if (pix < 0) {
        for (int c = tid; c < C; c += blockDim.x) y[c] = __float2half(0.f);
        return;
    }
    const float* xr = x + (size_t)pix * C;
    float s = 0.f, s2 = 0.f;
    for (int c = tid; c < C; c += blockDim.x) { float v = xr[c]; s += v; s2 += v * v; }
    __shared__ float red[64];
    for (int o = 16; o; o >>= 1) {
        s  += __shfl_xor_sync(0xffffffffu, s, o);
        s2 += __shfl_xor_sync(0xffffffffu, s2, o);
    }
    int warp = tid >> 5, lane = tid & 31;
    if (!lane) { red[warp] = s; red[32 + warp] = s2; }
    __syncthreads();
    if (tid < 32) {
        float a  = (tid < 8) ? red[tid]      : 0.f;
        float b2 = (tid < 8) ? red[32 + tid] : 0.f;
        for (int o = 4; o; o >>= 1) {
            a  += __shfl_xor_sync(0xffffffffu, a, o);
            b2 += __shfl_xor_sync(0xffffffffu, b2, o);
        }
        if (!tid) { red[0] = a; red[1] = b2; }
    }
    __syncthreads();
    float mu  = red[0] / (float)C;
    float var = red[1] / (float)C - mu * mu;
    float inv = rsqrtf(var + EPS);
    for (int c = tid; c < C; c += blockDim.x)
        y[c] = __float2half((xr[c] - mu) * inv * sc[c] + bi[c]);
}

// ---------------- LN over contiguous rows (x1 -> h2 fp16) -----------------
__global__ void ln_rows_kernel(const float* __restrict__ in,
                               const float* __restrict__ sc,
                               const float* __restrict__ bi) {
    int t = blockIdx.x;
    int tid = threadIdx.x;
    const float* xr = in + (size_t)t * C;
    __half* y = g_h2_h + (size_t)t * C;
    float s = 0.f, s2 = 0.f;
    for (int c = tid; c < C; c += blockDim.x) { float v = xr[c]; s += v; s2 += v * v; }
    __shared__ float red[64];
    for (int o = 16; o; o >>= 1) {
        s  += __shfl_xor_sync(0xffffffffu, s, o);
        s2 += __shfl_xor_sync(0xffffffffu, s2, o);
    }
    int warp = tid >> 5, lane = tid & 31;
    if (!lane) { red[warp] = s; red[32 + warp] = s2; }
    __syncthreads();
    if (tid < 32) {
        float a  = (tid < 8) ? red[tid]      : 0.f;
        float b2 = (tid < 8) ? red[32 + tid] : 0.f;
        for (int o = 4; o; o >>= 1) {
            a  += __shfl_xor_sync(0xffffffffu, a, o);
            b2 += __shfl_xor_sync(0xffffffffu, b2, o);
        }
        if (!tid) { red[0] = a; red[1] = b2; }
    }
    __syncthreads();
    float mu  = red[0] / (float)C;
    float var = red[1] / (float)C - mu * mu;
    float inv = rsqrtf(var + EPS);
    for (int c = tid; c < C; c += blockDim.x)
        y[c] = __float2half((xr[c] - mu) * inv * sc[c] + bi[c]);
}

// ---------------- fp16 tensor-core GEMM v8 (R15, validated) ----------------
constexpr int HG_RS = 72;                       // halfs per smem row
constexpr int HG_STG = 128 * HG_RS;             // halfs per stage per array
constexpr int HG_SMEM = 3 * HG_STG * 2 * 2;     // bytes (A+B, 3 stages)

template <int MODE>
__global__ void __launch_bounds__(256, 2)
hgemm_kernel(const __half* __restrict__ A,
             const __half* __restrict__ Bt,
             const float* __restrict__ bias,
             const float* __restrict__ aux,
             void* __restrict__ CoutV,
             int M, int N, int K) {
    extern __shared__ __half hsm[];
    __half* Asm = hsm;                 // 3 stages x HG_STG
    __half* Bsm = hsm + 3 * HG_STG;
    float*  Cf = (float*)CoutV;
    __half* Ch = (__half*)CoutV;

    int tid  = threadIdx.x;
    int warp = tid >> 5, lane = tid & 31;
    int wm = warp >> 1, wn = warp & 1;     // 4 x 2 warp grid
    int row0 = blockIdx.y * 128, col0 = blockIdx.x * 128;
    int r = lane >> 2, cq = lane & 3;
    int g = lane >> 3, rowin = lane & 7;

    int srow = tid >> 3, scp = tid & 7;
    const __half* AgI[4];
    const __half* BgI[4];
    uint32_t off[4];
    bool aok[4];
#pragma unroll
    for (int i = 0; i < 4; i++) {
        int row = srow + 32 * i;
        aok[i] = (row0 + row) < M;
        AgI[i] = A + (size_t)(row0 + row) * K + scp * 8;
        BgI[i] = Bt + (size_t)(col0 + row) * K + scp * 8;
        off[i] = (uint32_t)(row * HG_RS + scp * 8) * 2;
    }
    uint32_t abase = smem_u32(Asm);
    uint32_t bbase = smem_u32(Bsm);

    uint32_t a_l = 2u * (uint32_t)(((g & 1) * 8 + rowin) * HG_RS + (g >> 1) * 8);
    uint32_t b_l = 2u * (uint32_t)(((g >> 1) * 8 + rowin) * HG_RS + (g & 1) * 8);

    auto issue = [&](int t) {
        int s = t % 3;
        uint32_t ao = abase + (uint32_t)s * HG_STG * 2;
        uint32_t bo = bbase + (uint32_t)s * HG_STG * 2;
#pragma unroll
        for (int i = 0; i < 4; i++) {
            uint32_t asz = aok[i] ? 16u : 0u;
            asm volatile("cp.async.cg.shared.global [%0], [%1], 16, %2;"
                         :: "r"(ao + off[i]), "l"(AgI[i] + (size_t)t * 64),
                            "r"(asz) : "memory");
            asm volatile("cp.async.cg.shared.global [%0], [%1], 16;"
                         :: "r"(bo + off[i]), "l"(BgI[i] + (size_t)t * 64)
                         : "memory");
        }
    };

    int nk = K >> 6;   // BK=64
    issue(0);
    asm volatile("cp.async.commit_group;" ::: "memory");
    issue(1);
    asm volatile("cp.async.commit_group;" ::: "memory");

    float acc[2][8][4] = {};

    for (int t = 0; t < nk; t++) {
        asm volatile("cp.async.wait_group 1;" ::: "memory");
        __syncthreads();
        if (t + 2 < nk) issue(t + 2);
        asm volatile("cp.async.commit_group;" ::: "memory");   // always

        uint32_t asb = abase + (uint32_t)(t % 3) * HG_STG * 2;
        uint32_t bsb = bbase + (uint32_t)(t % 3) * HG_STG * 2;
#pragma unroll
        for (int ks = 0; ks < 4; ks++) {
            uint32_t k0b = (uint32_t)(ks * 16) * 2;
            uint32_t af[2][4], bq[4][4];
#pragma unroll
            for (int mt = 0; mt < 2; mt++)
                ldsm_x4(af[mt],
                        asb + 2u * (uint32_t)((wm * 32 + mt * 16) * HG_RS) + k0b + a_l);
#pragma unroll
            for (int p = 0; p < 4; p++)
                ldsm_x4(bq[p],
                        bsb + 2u * (uint32_t)((wn * 64 + p * 16) * HG_RS) + k0b + b_l);
#pragma unroll
            for (int nt = 0; nt < 8; nt++) {
                uint32_t b0 = bq[nt >> 1][(nt & 1) * 2];
                uint32_t b1 = bq[nt >> 1][(nt & 1) * 2 + 1];
#pragma unroll
                for (int mt = 0; mt < 2; mt++)
                    mma_f16(acc[mt][nt], af[mt], b0, b1);
            }
        }
    }

#pragma unroll
    for (int mt = 0; mt < 2; mt++) {
        int rA = row0 + wm * 32 + mt * 16 + r;
        int rB = rA + 8;
        bool okA = rA < M, okB = rB < M;
        int pixA = -1, pixB = -1;
        if (MODE == 1) {
            if (okA) pixA = winrow_to_pixel(rA);
            if (okB) pixB = winrow_to_pixel(rB);
        }
#pragma unroll
        for (int nt = 0; nt < 8; nt++) {
            int cb = col0 + wn * 64 + nt * 8 + cq * 2;
#pragma unroll
            for (int half = 0; half < 2; half++) {
                int rr = half ? rB : rA;
                bool ok = half ? okB : okA;
                if (!ok) continue;
                float v0 = acc[mt][nt][half * 2 + 0] + bias[cb];
                float v1 = acc[mt][nt][half * 2 + 1] + bias[cb + 1];
                if (MODE == 0) {
                    *(half2*)(Ch + (size_t)rr * N + cb) = __floats2half2_rn(v0, v1);
                } else if (MODE == 1) {
                    int pix = half ? pixB : pixA;
                    if (pix >= 0) {
                        Cf[(size_t)pix * N + cb]     = aux[(size_t)pix * N + cb] + v0;
                        Cf[(size_t)pix * N + cb + 1] = aux[(size_t)pix * N + cb + 1] + v1;
                    }
                } else if (MODE == 2) {
                    *(half2*)(Ch + (size_t)rr * N + cb) =
                        __floats2half2_rn(fast_gelu(v0), fast_gelu(v1));
                } else {
                    Cf[(size_t)rr * N + cb]     = aux[(size_t)rr * N + cb] + v0;
                    Cf[(size_t)rr * N + cb + 1] = aux[(size_t)rr * N + cb + 1] + v1;
                }
            }
        }
    }
}

// ---------------- fused attention v5: fp16 rel tables + fp16 probs ---------
// Smem ~69KB -> 3 CTAs/SM. Bias loop traffic halved (half2 RH/RW).
constexpr int ATTN_SMEM_U32 =
    L * 33 +        // Ks2 half2
    L * 32 +        // Vs2 half2
    RELN * 33 * 2 + // RH2 + RW2 half2 (row stride 33 u32)
    8 * 132 +       // per-warp q pair (fp32)
    8 * 200 +       // per-warp probs half2 (pA,pB)
    8 * 64;         // per-warp bias dots (fp32)
constexpr int ATTN_SMEM_BYTES = ATTN_SMEM_U32 * 4;

__global__ void attn_kernel(const float* __restrict__ rph,
                            const float* __restrict__ rpw) {
    extern __shared__ uint32_t smu[];
    half2* Ks2 = (half2*)smu;                  // [l*33 + d2]
    half2* Vs2 = Ks2 + L * 33;                 // [k*32 + lane]
    half2* RH2 = Vs2 + L * 32;                 // [r*33 + d2]
    half2* RW2 = RH2 + RELN * 33;
    float* qb  = (float*)(RW2 + RELN * 33);
    half2* pbk = (half2*)(qb + 8 * 132);       // 8 warps x 200
    float* bb  = (float*)(pbk + 8 * 200);

    int wh = blockIdx.x;
    int nw = wh / HEADS, head = wh - nw * HEADS;
    int tid = threadIdx.x;
    size_t base = (size_t)nw * L * C3 + head * HD;

    for (int idx = tid; idx < L * 32; idx += 256) {
        int l = idx >> 5, d2 = idx & 31;
        Ks2[l * 33 + d2] = *(const half2*)&g_qkv_h[base + (size_t)l * C3 + C + 2 * d2];
        Vs2[l * 32 + d2] = *(const half2*)&g_qkv_h[base + (size_t)l * C3 + 2 * C + 2 * d2];
    }
    for (int idx = tid; idx < RELN * 32; idx += 256) {
        int r = idx >> 5, d2 = idx & 31;
        float2 h = *(const float2*)&rph[r * HD + 2 * d2];
        float2 w = *(const float2*)&rpw[r * HD + 2 * d2];
        RH2[r * 33 + d2] = __floats2half2_rn(h.x, h.y);
        RW2[r * 33 + d2] = __floats2half2_rn(w.x, w.y);
    }
    __syncthreads();

    int warp = tid >> 5, lane = tid & 31;
    float* qv0 = qb + warp * 132;
    float* qv1 = qv0 + 66;
    half2* pp  = pbk + warp * 200;
    float* bw_ = bb + warp * 64;

    int koff[7];
    int kiL[7], kjL[7];
    bool ok[7];
#pragma unroll
    for (int s = 0; s < 7; s++) {
        int k = lane + 32 * s;
        ok[s] = (k < L);
        int kc = ok[s] ? k : (L - 1);
        kiL[s] = kc / WS;
        kjL[s] = kc - kiL[s] * WS;
        koff[s] = kc * 33;
    }

    for (int p = warp; p < L / 2; p += 8) {
        int q0 = 2 * p, q1 = q0 + 1;
        {
            float2 a = __half22float2(
                *(const half2*)&g_qkv_h[base + (size_t)q0 * C3 + lane * 2]);
            float2 b = __half22float2(
                *(const half2*)&g_qkv_h[base + (size_t)q1 * C3 + lane * 2]);
            *(float2*)&qv0[lane * 2] = a;
            *(float2*)&qv1[lane * 2] = b;
        }
        __syncwarp();

        int qi = q0 / WS, qj0 = q0 - qi * WS, qj1 = qj0 + 1;

        // bias dots: lanes 0..27, fp16 tables
        if (lane < 28) {
            int ksub = lane % 14;
            int qsel = lane / 14;
            const float* qp = qsel ? qv1 : qv0;
            const half2* hp = RH2 + (qi - ksub + WS - 1) * 33;
            int qj = qsel ? qj1 : qj0;
            const half2* wp = RW2 + (qj - ksub + WS - 1) * 33;
            float d1 = 0.f, d2a = 0.f;
#pragma unroll 8
            for (int d2 = 0; d2 < 32; d2++) {
                float2 q2 = *(const float2*)&qp[2 * d2];
                float2 h2 = __half22float2(hp[d2]);
                float2 w2 = __half22float2(wp[d2]);
                d1  = fmaf(q2.x, h2.x, d1);  d1  = fmaf(q2.y, h2.y, d1);
                d2a = fmaf(q2.x, w2.x, d2a); d2a = fmaf(q2.y, w2.y, d2a);
            }
            bw_[qsel * 14 + ksub] = d1;
            bw_[32 + qsel * 14 + ksub] = d2a;
        }
        __syncwarp();

        float sA[7] = {}, sB[7] = {};
#pragma unroll 8
        for (int d2 = 0; d2 < 32; d2++) {
            float2 qa2 = *(const float2*)&qv0[2 * d2];
            float2 qc2 = *(const float2*)&qv1[2 * d2];
#pragma unroll
            for (int s = 0; s < 7; s++) {
                float2 kf = __half22float2(Ks2[koff[s] + d2]);
                sA[s] = fmaf(qa2.x, kf.x, sA[s]);
                sA[s] = fmaf(qa2.y, kf.y, sA[s]);
                sB[s] = fmaf(qc2.x, kf.x, sB[s]);
                sB[s] = fmaf(qc2.y, kf.y, sB[s]);
            }
        }
        float ltA[7], ltB[7];
#pragma unroll
        for (int s = 0; s < 7; s++) {
            float bhA = bw_[kiL[s]],        bhB = bw_[14 + kiL[s]];
            float bwA = bw_[32 + kjL[s]],   bwB = bw_[46 + kjL[s]];
            ltA[s] = ok[s] ? (sA[s] * SCALE + bhA + bwA) : -1e30f;
            ltB[s] = ok[s] ? (sB[s] * SCALE + bhB + bwB) : -1e30f;
        }

        float mxA = ltA[0], mxB = ltB[0];
#pragma unroll
        for (int s = 1; s < 7; s++) { mxA = fmaxf(mxA, ltA[s]); mxB = fmaxf(mxB, ltB[s]); }
        for (int o = 16; o; o >>= 1) {
            mxA = fmaxf(mxA, __shfl_xor_sync(0xffffffffu, mxA, o));
            mxB = fmaxf(mxB, __shfl_xor_sync(0xffffffffu, mxB, o));
        }
        float smA = 0.f, smB = 0.f;
#pragma unroll
        for (int s = 0; s < 7; s++) {
            ltA[s] = expf(ltA[s] - mxA); smA += ltA[s];
            ltB[s] = expf(ltB[s] - mxB); smB += ltB[s];
        }
        for (int o = 16; o; o >>= 1) {
            smA += __shfl_xor_sync(0xffffffffu, smA, o);
            smB += __shfl_xor_sync(0xffffffffu, smB, o);
        }
        float ivA = 1.f / smA, ivB = 1.f / smB;
#pragma unroll
        for (int s = 0; s < 7; s++) {
            int k = lane + 32 * s;
            if (k < L) pp[k] = __floats2half2_rn(ltA[s] * ivA, ltB[s] * ivB);
        }
        __syncwarp();

        float a0 = 0.f, a1 = 0.f, b0 = 0.f, b1 = 0.f;
#pragma unroll 4
        for (int k = 0; k < L; k++) {
            float2 vf = __half22float2(Vs2[k * 32 + lane]);
            float2 pr = __half22float2(pp[k]);
            a0 = fmaf(pr.x, vf.x, a0);
            a1 = fmaf(pr.x, vf.y, a1);
            b0 = fmaf(pr.y, vf.x, b0);
            b1 = fmaf(pr.y, vf.y, b1);
        }
        size_t orow = ((size_t)nw * L + q0) * C + head * HD + lane * 2;
        *(half2*)&g_owin_h[orow]     = __floats2half2_rn(a0, a1);
        *(half2*)&g_owin_h[orow + C] = __floats2half2_rn(b0, b1);
        __syncwarp();
    }
}

// ---------------- launch ---------------------------------------------------
extern "C" void kernel_launch(void* const* d_in, const int* in_sizes, int n_in,
                              void* d_out, int out_size) {
    const float* x      = (const float*)d_in[0];
    const float* n1s    = (const float*)d_in[1];
    const float* n1b    = (const float*)d_in[2];
    const float* qkvw   = (const float*)d_in[3];
    const float* qkvb   = (const float*)d_in[4];
    const float* rph    = (const float*)d_in[5];
    const float* rpw    = (const float*)d_in[6];
    const float* projw  = (const float*)d_in[7];
    const float* projb  = (const float*)d_in[8];
    const float* n2s    = (const float*)d_in[9];
    const float* n2b    = (const float*)d_in[10];
    const float* fc1w   = (const float*)d_in[11];
    const float* fc1b   = (const float*)d_in[12];
    const float* fc2w   = (const float*)d_in[13];
    const float* fc2b   = (const float*)d_in[14];
    float* out = (float*)d_out;

    cudaFuncSetAttribute(attn_kernel, cudaFuncAttributeMaxDynamicSharedMemorySize,
                         ATTN_SMEM_BYTES);
    cudaFuncSetAttribute(hgemm_kernel<0>, cudaFuncAttributeMaxDynamicSharedMemorySize, HG_SMEM);
    cudaFuncSetAttribute(hgemm_kernel<1>, cudaFuncAttributeMaxDynamicSharedMemorySize, HG_SMEM);
    cudaFuncSetAttribute(hgemm_kernel<2>, cudaFuncAttributeMaxDynamicSharedMemorySize, HG_SMEM);
    cudaFuncSetAttribute(hgemm_kernel<3>, cudaFuncAttributeMaxDynamicSharedMemorySize, HG_SMEM);

    __half* ywin;  cudaGetSymbolAddress((void**)&ywin,  g_ywin_h);
    __half* qkv;   cudaGetSymbolAddress((void**)&qkv,   g_qkv_h);
    __half* owin;  cudaGetSymbolAddress((void**)&owin,  g_owin_h);
    float*  x1;    cudaGetSymbolAddress((void**)&x1,    g_x1);
    __half* h2;    cudaGetSymbolAddress((void**)&h2,    g_h2_h);
    __half* m1;    cudaGetSymbolAddress((void**)&m1,    g_m1_h);
    __half* qkvwt; cudaGetSymbolAddress((void**)&qkvwt, g_qkvw_t);
    __half* projwt;cudaGetSymbolAddress((void**)&projwt,g_projw_t);
    __half* fc1wt; cudaGetSymbolAddress((void**)&fc1wt, g_fc1w_t);
    __half* fc2wt; cudaGetSymbolAddress((void**)&fc2wt, g_fc2w_t);

    // 0) all weight transposes in ONE launch
    wt_all_kernel<<<WT_BLOCKS, dim3(32, 8)>>>(qkvw, qkvwt, projw, projwt,
                                              fc1w, fc1wt, fc2w, fc2wt);

    // 1) LN1 + window partition (zero-pad), fp16 out
    ln1_gather_kernel<<<NT, 256>>>(x, n1s, n1b);

    // 2) qkv = ywin @ qkv_w + qkv_b           (19600 x 2304 x 768), fp16 out
    {
        dim3 grid(C3 / 128, (NT + 127) / 128);
        hgemm_kernel<0><<<grid, 256, HG_SMEM>>>(ywin, qkvwt, qkvb, nullptr, qkv, NT, C3, C);
    }

    // 3) fused windowed attention v5, fp16 out
    attn_kernel<<<NW * HEADS, 256, ATTN_SMEM_BYTES>>>(rph, rpw);

    // 4) x1 = shortcut + (owin @ proj_w + proj_b)  (scatter, crop padding)
    {
        dim3 grid(C / 128, (NT + 127) / 128);
        hgemm_kernel<1><<<grid, 256, HG_SMEM>>>(owin, projwt, projb, x, x1, NT, C, C);
    }

    // 5) LN2 -> fp16
    ln_rows_kernel<<<NP, 256>>>(x1, n2s, n2b);

    // 6) m1 = gelu(h2 @ fc1_w + fc1_b)        (16384 x 3072 x 768), fp16 out
    {
        dim3 grid(HID / 128, NP / 128);
        hgemm_kernel<2><<<grid, 256, HG_SMEM>>>(h2, fc1wt, fc1b, nullptr, m1, NP, HID, C);
    }

    // 7) out = x1 + m1 @ fc2_w + fc2_b        (16384 x 768 x 3072), fp32 out
    {
        dim3 grid(C / 128, NP / 128);
        hgemm_kernel<3><<<grid, 256, HG_SMEM>>>(m1, fc2wt, fc2b, x1, out, NP, C, HID);
    }
}